// round 13
// baseline (speedup 1.0000x reference)
#include <cuda_runtime.h>
#include <math.h>

#define TPB 128

__device__ __forceinline__ float2 cmul(float2 a, float2 b) {
    float2 r;
    r.x = fmaf(-a.y, b.y, a.x * b.x);
    r.y = fmaf( a.x, b.y, a.y * b.x);
    return r;
}

__global__ __launch_bounds__(TPB) void pmsn_kernel(
    const float* __restrict__ log_dt,
    const float* __restrict__ log_A_real,
    const float* __restrict__ A_imag,
    const float* __restrict__ VinvB_real,
    const float* __restrict__ VinvB_imag,
    const float* __restrict__ CV_real,
    const float* __restrict__ CV_imag,
    float* __restrict__ out, int L)
{
    const int t    = threadIdx.x;
    const int warp = t >> 5;
    const int lane = t & 31;
    const int h    = blockIdx.x * 2 + (warp >> 1);  // 2 h per block
    const int w2   = warp & 1;                      // which half of the row

    // ---- lanes 0,1: transcendental bundle + coef for paired state s=lane ----
    float A1re = 0.f, A1im = 0.f, cfre = 0.f, cfim = 0.f;
    if (lane < 2) {
        const int s = lane;
        // s-th state with A_imag > 0 (conjugate-pair representative; validated R9-R12)
        int n = 3, cnt = 0;
#pragma unroll
        for (int k = 0; k < 4; ++k) {
            const float a = A_imag[h * 4 + k];
            if (a > 0.0f) { if (cnt == s) n = k; ++cnt; }
        }
        const int idx = h * 4 + n;

        const float dt  = expf(log_dt[h]);
        const float Are = -expf(log_A_real[idx]);
        const float Aim = A_imag[idx];
        const float adr = Are * dt;
        const float adi = Aim * dt;                  // |adi| < ~2 rad

        float sn, cs;
        sincosf(adi, &sn, &cs);
        const float m = expf(adr);
        A1re = m * cs;
        A1im = m * sn;

        // coef = 2 * C * (A_bar - 1)/A * B
        const float inv = 1.0f / fmaf(Are, Are, Aim * Aim);
        const float iAr =  Are * inv, iAi = -Aim * inv;
        const float mr = A1re - 1.0f, mi = A1im;
        const float qr = mr * iAr - mi * iAi;
        const float qi = mr * iAi + mi * iAr;
        const float Br = VinvB_real[idx], Bi = VinvB_imag[idx];
        const float bbr = qr * Br - qi * Bi;
        const float bbi = qr * Bi + qi * Br;
        const float Cr = CV_real[idx], Ci = CV_imag[idx];
        cfre = 2.0f * (Cr * bbr - Ci * bbi);
        cfim = 2.0f * (Cr * bbi + Ci * bbr);
    }

    // broadcast both states' A_bar and coef
    const float a1r[2] = { __shfl_sync(0xffffffffu, A1re, 0), __shfl_sync(0xffffffffu, A1re, 1) };
    const float a1i[2] = { __shfl_sync(0xffffffffu, A1im, 0), __shfl_sync(0xffffffffu, A1im, 1) };
    const float cfr[2] = { __shfl_sync(0xffffffffu, cfre, 0), __shfl_sync(0xffffffffu, cfre, 1) };
    const float cfi[2] = { __shfl_sync(0xffffffffu, cfim, 0), __shfl_sync(0xffffffffu, cfim, 1) };

    // ---- per-lane setup: binary exponentiation, no smem, no barrier ----
    const int e = lane + 32 * w2;                    // l = 4e + i + 256j
    float xc[2][4], xp[2][4], pn[2], qn[2];
#pragma unroll
    for (int s = 0; s < 2; ++s) {
        const float2 A1 = make_float2(a1r[s], a1i[s]);
        const float2 A2 = cmul(A1, A1);
        const float2 A3 = cmul(A2, A1);
        const float2 A4 = cmul(A2, A2);

        // res = A4^e (6 bits), base ends at A4^64 = A_bar^256 = stride S
        float2 res  = make_float2(1.0f, 0.0f);
        float2 base = A4;
#pragma unroll
        for (int b = 0; b < 6; ++b) {
            if ((e >> b) & 1) res = cmul(res, base);
            base = cmul(base, base);
        }
        const float2 S = base;

        const float2 v  = cmul(make_float2(cfr[s], cfi[s]), res);  // j=0 state
        const float2 u  = cmul(v, S);                              // j=1 state
        xp[s][0] = v.x;
        xc[s][0] = u.x;
        // phases 1..3 via rotators (cos, -sin) of A_bar^{1,2,3}
        xp[s][1] = fmaf(v.y, -A1.y, v.x * A1.x);
        xc[s][1] = fmaf(u.y, -A1.y, u.x * A1.x);
        xp[s][2] = fmaf(v.y, -A2.y, v.x * A2.x);
        xc[s][2] = fmaf(u.y, -A2.y, u.x * A2.x);
        xp[s][3] = fmaf(v.y, -A3.y, v.x * A3.x);
        xc[s][3] = fmaf(u.y, -A3.y, u.x * A3.x);

        pn[s] = S.x + S.x;
        qn[s] = -fmaf(S.x, S.x, S.y * S.y);
    }

    float* __restrict__ orow = out + (size_t)h * (size_t)L + 4 * e;
    const int NJ = L >> 8;    // L / 256 = 16

    *(float4*)orow = make_float4(xp[0][0] + xp[1][0], xp[0][1] + xp[1][1],
                                 xp[0][2] + xp[1][2], xp[0][3] + xp[1][3]);
    if (NJ > 1)
        *(float4*)(orow + 256) = make_float4(xc[0][0] + xc[1][0], xc[0][1] + xc[1][1],
                                             xc[0][2] + xc[1][2], xc[0][3] + xc[1][3]);

    // Chebyshev: x_j = p*x_{j-1} + q*x_{j-2}  (2 states x 4 phases)
#pragma unroll 14
    for (int j = 2; j < NJ; ++j) {
#pragma unroll
        for (int s = 0; s < 2; ++s) {
#pragma unroll
            for (int i = 0; i < 4; ++i) {
                const float xn = fmaf(pn[s], xc[s][i], qn[s] * xp[s][i]);
                xp[s][i] = xc[s][i];
                xc[s][i] = xn;
            }
        }
        *(float4*)(orow + (size_t)j * 256) =
            make_float4(xc[0][0] + xc[1][0], xc[0][1] + xc[1][1],
                        xc[0][2] + xc[1][2], xc[0][3] + xc[1][3]);
    }
}

extern "C" void kernel_launch(void* const* d_in, const int* in_sizes, int n_in,
                              void* d_out, int out_size) {
    const float* log_dt     = (const float*)d_in[0];
    const float* log_A_real = (const float*)d_in[1];
    const float* A_imag     = (const float*)d_in[2];
    const float* VinvB_real = (const float*)d_in[3];
    const float* VinvB_imag = (const float*)d_in[4];
    const float* CV_real    = (const float*)d_in[5];
    const float* CV_imag    = (const float*)d_in[6];
    const int H = in_sizes[0];               // 2048
    const int L = out_size / H;              // 4096
    pmsn_kernel<<<H / 2, TPB>>>(log_dt, log_A_real, A_imag,
                                VinvB_real, VinvB_imag,
                                CV_real, CV_imag, (float*)d_out, L);
}

// round 14
// speedup vs baseline: 1.4455x; 1.4455x over previous
#include <cuda_runtime.h>
#include <math.h>

#define TPB 128
#define NT 26
// per (h, paired-state) table (float2):
// [0..15]  P4[r] = A_bar^(4r)
// [16..19] W[q]  = A_bar^(64q)
// [20]     S     = A_bar^256
// [21..23] rot i = (cos, -sin) of A_bar^i, i=1..3
// [24]     (2 Re S, -|S|^2)
// [25]     2 * C * B_bar

__device__ __forceinline__ float2 cmul(float2 a, float2 b) {
    float2 r;
    r.x = fmaf(-a.y, b.y, a.x * b.x);
    r.y = fmaf( a.x, b.y, a.y * b.x);
    return r;
}

__device__ __forceinline__ float sel4(float4 v, int k) {
    float r = v.x;
    if (k == 1) r = v.y;
    if (k == 2) r = v.z;
    if (k == 3) r = v.w;
    return r;
}

__global__ __launch_bounds__(TPB) void pmsn_kernel(
    const float* __restrict__ log_dt,
    const float* __restrict__ log_A_real,
    const float* __restrict__ A_imag,
    const float* __restrict__ VinvB_real,
    const float* __restrict__ VinvB_imag,
    const float* __restrict__ CV_real,
    const float* __restrict__ CV_imag,
    float* __restrict__ out, int L)
{
    __shared__ float2 Tsm[2][2][NT];          // [hh][s][entry]
    const int t = threadIdx.x;
    const size_t hbase = (size_t)blockIdx.x * 2;

    // ---- fused prologue: 4 lanes, one job = (hh, s); ALL loads issued in parallel ----
    if (t < 4) {
        const int hh = t >> 1;
        const int s  = t & 1;
        const int h  = (int)hbase + hh;

        // parallel LDG.128 of all four states' params + log_dt (single latency round)
        const float  ld  = log_dt[h];
        const float4 ai4 = ((const float4*)A_imag)[h];
        const float4 lar = ((const float4*)log_A_real)[h];
        const float4 br4 = ((const float4*)VinvB_real)[h];
        const float4 bi4 = ((const float4*)VinvB_imag)[h];
        const float4 cr4 = ((const float4*)CV_real)[h];
        const float4 ci4 = ((const float4*)CV_imag)[h];

        // s-th state with A_imag > 0 (conjugate-pair representative; validated R9-R13)
        int n = 3, cnt = 0;
#pragma unroll
        for (int k = 0; k < 4; ++k) {
            const float a = sel4(ai4, k);
            if (a > 0.0f) { if (cnt == s) n = k; ++cnt; }
        }

        const float dt  = expf(ld);
        const float Are = -expf(sel4(lar, n));
        const float Aim = sel4(ai4, n);
        const float adr = Are * dt;
        const float adi = Aim * dt;               // |adi| < ~2 rad

        float sn, cs;
        sincosf(adi, &sn, &cs);
        const float m = expf(adr);
        const float2 A1 = make_float2(m * cs, m * sn);
        const float2 A2 = cmul(A1, A1);
        const float2 A3 = cmul(A2, A1);

        float2 T[NT];
        T[0] = make_float2(1.0f, 0.0f);
        T[1] = cmul(A2, A2);                      // A4
        // tree-ordered powers of A4: chain depth ~4
#pragma unroll
        for (int r = 2; r < 16; ++r)
            T[r] = cmul(T[r >> 1], T[r - (r >> 1)]);
        const float2 A64 = cmul(T[8], T[8]);      // A_bar^64
        T[16] = make_float2(1.0f, 0.0f);
        T[17] = A64;
        T[18] = cmul(A64, A64);                   // A_bar^128
        T[19] = cmul(T[18], A64);                 // A_bar^192
        const float2 S = cmul(T[18], T[18]);      // A_bar^256
        T[20] = S;
        T[21] = make_float2(A1.x, -A1.y);
        T[22] = make_float2(A2.x, -A2.y);
        T[23] = make_float2(A3.x, -A3.y);
        T[24] = make_float2(S.x + S.x, -fmaf(S.x, S.x, S.y * S.y));

        // coef = 2 * C * (A_bar - 1)/A * B
        const float inv = 1.0f / fmaf(Are, Are, Aim * Aim);
        const float iAr =  Are * inv, iAi = -Aim * inv;
        const float mr = A1.x - 1.0f, mi = A1.y;
        const float qr = mr * iAr - mi * iAi;
        const float qi = mr * iAi + mi * iAr;
        const float Br = sel4(br4, n), Bi = sel4(bi4, n);
        const float bbr = qr * Br - qi * Bi;
        const float bbi = qr * Bi + qi * Br;
        const float Cr = sel4(cr4, n), Ci = sel4(ci4, n);
        T[25] = make_float2(2.0f * (Cr * bbr - Ci * bbi),
                            2.0f * (Cr * bbi + Ci * bbr));

#pragma unroll
        for (int i = 0; i < NT; ++i) Tsm[hh][s][i] = T[i];
    }
    __syncthreads();

    // ---- main: thread covers h = hbase + (t>>6), l = 4u + i + 256j ----
    const int hh = t >> 6;
    const int u  = t & 63;
    const int q  = u >> 4;
    const int r  = u & 15;

    float xc[2][4], xp[2][4], pn[2], qn[2];
#pragma unroll
    for (int s = 0; s < 2; ++s) {
        const float2* __restrict__ T = Tsm[hh][s];
        const float2 w  = cmul(T[16 + q], T[r]);     // A_bar^(4u)
        const float2 v  = cmul(w, T[25]);            // j=0 state
        const float2 u2 = cmul(v, T[20]);            // j=1 state
        xp[s][0] = v.x;
        xc[s][0] = u2.x;
#pragma unroll
        for (int i = 0; i < 3; ++i) {
            const float2 ro = T[21 + i];             // (cos, -sin)
            xp[s][i + 1] = fmaf(v.y,  ro.y, v.x  * ro.x);
            xc[s][i + 1] = fmaf(u2.y, ro.y, u2.x * ro.x);
        }
        pn[s] = T[24].x;
        qn[s] = T[24].y;
    }

    float* __restrict__ orow = out + (hbase + hh) * (size_t)L + 4 * u;
    const int NJ = L >> 8;            // L / 256 = 16

    __stcs((float4*)orow,
           make_float4(xp[0][0] + xp[1][0], xp[0][1] + xp[1][1],
                       xp[0][2] + xp[1][2], xp[0][3] + xp[1][3]));
    if (NJ > 1)
        __stcs((float4*)(orow + 256),
               make_float4(xc[0][0] + xc[1][0], xc[0][1] + xc[1][1],
                           xc[0][2] + xc[1][2], xc[0][3] + xc[1][3]));

#pragma unroll 14
    for (int j = 2; j < NJ; ++j) {
#pragma unroll
        for (int s = 0; s < 2; ++s) {
#pragma unroll
            for (int i = 0; i < 4; ++i) {
                const float xn = fmaf(pn[s], xc[s][i], qn[s] * xp[s][i]);
                xp[s][i] = xc[s][i];
                xc[s][i] = xn;
            }
        }
        __stcs((float4*)(orow + (size_t)j * 256),
               make_float4(xc[0][0] + xc[1][0], xc[0][1] + xc[1][1],
                           xc[0][2] + xc[1][2], xc[0][3] + xc[1][3]));
    }
}

extern "C" void kernel_launch(void* const* d_in, const int* in_sizes, int n_in,
                              void* d_out, int out_size) {
    const float* log_dt     = (const float*)d_in[0];
    const float* log_A_real = (const float*)d_in[1];
    const float* A_imag     = (const float*)d_in[2];
    const float* VinvB_real = (const float*)d_in[3];
    const float* VinvB_imag = (const float*)d_in[4];
    const float* CV_real    = (const float*)d_in[5];
    const float* CV_imag    = (const float*)d_in[6];
    const int H = in_sizes[0];               // 2048
    const int L = out_size / H;              // 4096
    pmsn_kernel<<<H / 2, TPB>>>(log_dt, log_A_real, A_imag,
                                VinvB_real, VinvB_imag,
                                CV_real, CV_imag, (float*)d_out, L);
}